// round 11
// baseline (speedup 1.0000x reference)
#include <cuda_runtime.h>

// QSP expectation, single fused kernel, zero inter-block communication.
//
// Pair-merged chain: W(th)S(pa)W(th)S(pb) = [[A+B*c2, i*conj(B)*s2],
//                                            [i*B*s2,  conj(A)+conj(B)*c2]]
// with c2=cos2th, s2=sin2th and A=(u-v)/2, B=(u+v)/2, u=e^{i(pa+pb)},
// v=e^{i(pb-pa)} (phase-only constants). Each thread evaluates the 27-merged-
// step chain DIRECTLY at its own table grid points (exact, no DFT/Clenshaw),
// the block builds a 1024-interval cubic-coefficient table, then each thread
// evaluates 4 elements: range-reduce + one aligned LDS.128 + 3-fma Horner.

#define NPAIR 27
#define TSIZE 1024

__global__ void __launch_bounds__(512, 2)
qsp_fused(const float4* __restrict__ x4,
          const float*  __restrict__ phis,
          const float4* __restrict__ a4,
          const float*  __restrict__ bias,
          float4* __restrict__ out4,
          int nq)                       // nq = n/4
{
    __shared__ __align__(16) float4 sM[NPAIR];    // (Ax, Ay, Bx, By) per pair
    __shared__ float s0cs[2];
    __shared__ __align__(16) float g[TSIZE];      // g on the grid
    __shared__ __align__(16) float4 cf[TSIZE];    // cubic coeffs per interval

    const int t = threadIdx.x;                    // 0..511
    const int T = blockIdx.x * blockDim.x + t;
    const bool act = (T < nq);

    // ---- eval-path global loads issued FIRST (latency overlapped) ----
    float4 xv = make_float4(0.f, 0.f, 0.f, 0.f);
    float4 av = xv;
    if (act) { xv = x4[T]; av = a4[T]; }
    const float bb = bias[0];

    // ---- pair constants from phases (27 threads, 2 sincosf each) ----
    if (t < NPAIR) {
        const float pa = phis[2 * t + 1];
        const float pb = phis[2 * t + 2];
        float su, cu, sv, cv;
        sincosf(pa + pb, &su, &cu);    // u = e^{i(pa+pb)}
        sincosf(pb - pa, &sv, &cv);    // v = e^{i(pb-pa)}
        sM[t] = make_float4(0.5f * (cu - cv), 0.5f * (su - sv),    // A
                            0.5f * (cu + cv), 0.5f * (su + sv));   // B
    }
    if (t == 31) {
        float sp, cp; sincosf(phis[0], &sp, &cp);
        s0cs[0] = cp; s0cs[1] = sp;
    }
    __syncthreads();

    // ---- direct chain at grid points j = t and j + 512 (2 chains, ILP) ----
    {
        // 2*theta_j = pi * j / 512
        float sA, cA, sB, cB;
        sincospif((float)t * (1.0f / 512.0f), &sA, &cA);
        sincospif((float)(t + 512) * (1.0f / 512.0f), &sB, &cB);

        float x0a = 1.f, y0a = 0.f, x1a = 0.f, y1a = 0.f;
        float x0b = 1.f, y0b = 0.f, x1b = 0.f, y1b = 0.f;

        // 3-deep rolling prefetch of pair constants (broadcast LDS.128)
        float4 m0 = sM[0], m1 = sM[1], m2 = sM[2];

        #pragma unroll
        for (int k = 0; k < NPAIR; ++k) {
            const float Ax = m0.x, Ay = m0.y, Bx = m0.z, By = m0.w;
            m0 = m1; m1 = m2;
            if (k + 3 < NPAIR) m2 = sM[k + 3];

            // chain A
            {
                const float Ex = fmaf(Bx, cA, Ax), Ey = fmaf(By, cA, Ay);
                const float Fx = By * sA, Fy = Bx * sA;   // F=(-Fx,Fy), G=(Fx,Fy)
                const float nx0 = x0a*Ex - y0a*Ey - x1a*Fx - y1a*Fy;
                const float ny0 = x0a*Ey + y0a*Ex + x1a*Fy - y1a*Fx;
                const float nx1 = x0a*Fx - y0a*Fy + x1a*Ex + y1a*Ey;
                const float ny1 = x0a*Fy + y0a*Fx - x1a*Ey + y1a*Ex;
                x0a = nx0; y0a = ny0; x1a = nx1; y1a = ny1;
            }
            // chain B
            {
                const float Ex = fmaf(Bx, cB, Ax), Ey = fmaf(By, cB, Ay);
                const float Fx = By * sB, Fy = Bx * sB;
                const float nx0 = x0b*Ex - y0b*Ey - x1b*Fx - y1b*Fy;
                const float ny0 = x0b*Ey + y0b*Ex + x1b*Fy - y1b*Fx;
                const float nx1 = x0b*Fx - y0b*Fy + x1b*Ex + y1b*Ey;
                const float ny1 = x0b*Fy + y0b*Fx - x1b*Ey + y1b*Ex;
                x0b = nx0; y0b = ny0; x1b = nx1; y1b = ny1;
            }
        }

        // g = Re( e^{i phi0} * P00 )
        g[t]       = s0cs[0] * x0a - s0cs[1] * y0a;
        g[t + 512] = s0cs[0] * x0b - s0cs[1] * y0b;
    }
    __syncthreads();

    // ---- cubic monomial coefficients per interval ----
    #pragma unroll
    for (int r = 0; r < 2; ++r) {
        const int j = t + r * 512;
        const float gm = g[(j + TSIZE - 1) & (TSIZE - 1)];
        const float g0 = g[j];
        const float gp = g[(j + 1) & (TSIZE - 1)];
        const float gq = g[(j + 2) & (TSIZE - 1)];
        const float c1 = gp - gm * (1.0f/3.0f) - g0 * 0.5f - gq * (1.0f/6.0f);
        const float c2 = 0.5f * (gm + gp) - g0;
        const float c3 = (3.0f * (g0 - gp) + gq - gm) * (1.0f/6.0f);
        cf[j] = make_float4(g0, c1, c2, c3);
    }
    __syncthreads();

    // ---- evaluation: range-reduce + LDS.128 + Horner ----
    if (!act) return;

    const float SCALE = (float)TSIZE / 3.14159265358979323846f;
    float th[4] = {xv.x, xv.y, xv.z, xv.w};
    float res[4];
    #pragma unroll
    for (int e = 0; e < 4; ++e) {
        const float u  = th[e] * SCALE;
        const float fl = floorf(u);
        const float f  = u - fl;
        const int idx  = ((int)fl) & (TSIZE - 1);
        const float4 c = cf[idx];
        res[e] = fmaf(fmaf(fmaf(c.w, f, c.z), f, c.y), f, c.x);
    }

    out4[T] = make_float4(fmaf(av.x, res[0], bb), fmaf(av.y, res[1], bb),
                          fmaf(av.z, res[2], bb), fmaf(av.w, res[3], bb));
}

// ---------------------------------------------------------------------------
// Fallback for unexpected shapes (direct chain evaluation).
// ---------------------------------------------------------------------------
__global__ void __launch_bounds__(256)
qsp_generic(const float* __restrict__ x,
            const float* __restrict__ phis,
            const float* __restrict__ alphas,
            const float* __restrict__ bias,
            float* __restrict__ out,
            int n, int nsteps)
{
    __shared__ float pc[256], ps[256];
    __shared__ float s0c, s0s;
    int t = threadIdx.x;
    if (t < nsteps && t < 256) {
        float sp, cp; sincosf(phis[t + 1], &sp, &cp);
        pc[t] = cp; ps[t] = sp;
    }
    if (t == 0) {
        float sp, cp; sincosf(phis[0], &sp, &cp);
        s0c = cp; s0s = sp;
    }
    __syncthreads();

    const int i = blockIdx.x * blockDim.x + t;
    if (i >= n) return;

    float s, c; sincosf(x[i], &s, &c);
    float x0 = 1.0f, y0 = 0.0f, x1 = 0.0f, y1 = 0.0f;
    for (int k = 0; k < nsteps; ++k) {
        const float ec = (k < 256) ? pc[k] : cosf(phis[k + 1]);
        const float es = (k < 256) ? ps[k] : sinf(phis[k + 1]);
        const float ux = c * x0 - s * y1;
        const float uy = c * y0 + s * x1;
        const float vx = c * x1 - s * y0;
        const float vy = c * y1 + s * x0;
        x0 = ec * ux - es * uy;
        y0 = es * ux + ec * uy;
        x1 = ec * vx + es * vy;
        y1 = ec * vy - es * vx;
    }
    const float re = s0c * x0 - s0s * y0;
    out[i] = fmaf(alphas[i], re, bias[0]);
}

extern "C" void kernel_launch(void* const* d_in, const int* in_sizes, int n_in,
                              void* d_out, int out_size)
{
    const float* x      = (const float*)d_in[0];
    const float* phis   = (const float*)d_in[1];
    const float* alphas = (const float*)d_in[2];
    const float* bias   = (const float*)d_in[3];
    float* out = (float*)d_out;

    const int n      = in_sizes[0];
    const int nph    = in_sizes[1];
    const int nsteps = nph - 1;

    if (nsteps == 2 * NPAIR && (n & 3) == 0) {
        const int nq      = n >> 2;                   // float4 quads
        const int threads = 512;
        const int blocks  = (nq + threads - 1) / threads;   // 256 for n=524288
        qsp_fused<<<blocks, threads>>>((const float4*)x, phis,
                                       (const float4*)alphas, bias,
                                       (float4*)out, nq);
    } else {
        const int threads = 256;
        const int blocks  = (n + threads - 1) / threads;
        qsp_generic<<<blocks, threads>>>(x, phis, alphas, bias, out, n, nsteps);
    }
}

// round 12
// speedup vs baseline: 1.2601x; 1.2601x over previous
#include <cuda_runtime.h>

// QSP expectation, single fused kernel, zero inter-block communication.
//
// g(theta) = Re(e^{i phi0} P00) = sum_{j<=27} A_j cos(2j th) + B_j sin(2j th)
//   (pi-periodic, band-limited 54). Per block (2 per SM):
//   1) 54-step chain split into two 27-step halves (rows x cols, 128 thr)
//      at 64 samples -> exact table-based 64-pt DFT (8 accumulators).
//   2) 1024-entry table of g: 512 threads x 2 grid points, scalar Clenshaw
//      with 3-deep float2 coefficient prefetch.
//   3) monomial cubic coefficients per interval; eval = range-reduce +
//      one LDS.128 + 3-fma Horner, 4 elements/thread, early LDGs.

#define NSTEP 54
#define NHARM 27
#define NSAMP 64
#define TSIZE 1024

__global__ void __launch_bounds__(512, 2)
qsp_fused(const float4* __restrict__ x4,
          const float*  __restrict__ phis,
          const float4* __restrict__ a4,
          const float*  __restrict__ bias,
          float4* __restrict__ out4,
          int nq)                       // nq = n/4
{
    __shared__ float pc[NSTEP], ps[NSTEP];
    __shared__ float s0cs[2];
    __shared__ float lh[64 * 4], rh[64 * 4];
    __shared__ float gs[NSAMP];
    __shared__ float tab[NSAMP];
    __shared__ __align__(8)  float2 sAB[NHARM + 1];
    __shared__ __align__(16) float  g[TSIZE];
    __shared__ __align__(16) float4 cf[TSIZE];

    const int t = threadIdx.x;                    // 0..511
    const int T = blockIdx.x * blockDim.x + t;
    const bool act = (T < nq);

    // ---- eval-path global loads issued FIRST (latency hidden) ----
    float4 xv = make_float4(0.f, 0.f, 0.f, 0.f);
    float4 av = xv;
    if (act) { xv = x4[T]; av = a4[T]; }
    const float bb = bias[0];

    // ---- phase setup ----
    if (t < NSTEP) {
        float sp, cp; sincosf(phis[t + 1], &sp, &cp);   // accurate, one-time
        pc[t] = cp; ps[t] = sp;
    }
    if (t == 60) {
        float sp, cp; sincosf(phis[0], &sp, &cp);
        s0cs[0] = cp; s0cs[1] = sp;
    }
    if (t >= 64 && t < 64 + NSAMP) {
        const int i = t - 64;
        tab[i] = sinpif((float)i * (1.0f / 32.0f));     // sin(pi*i/32)
    }
    __syncthreads();

    // ---- chain split: 0-63 left rows, 64-127 right cols (transposed) ----
    if (t < 128) {
        const int i = t & 63;
        float s, c; sincospif((float)i * (1.0f / 64.0f), &s, &c);
        float x0, y0, x1, y1;
        if (t < 64) {
            x0 = 1.f; y0 = 0.f; x1 = 0.f; y1 = 0.f;
            #pragma unroll
            for (int k = 0; k < NHARM; ++k) {
                const float ec = pc[k], es = ps[k];
                const float ux = c * x0 - s * y1, uy = c * y0 + s * x1;
                const float vx = c * x1 - s * y0, vy = c * y1 + s * x0;
                x0 = ec * ux - es * uy; y0 = es * ux + ec * uy;
                x1 = ec * vx + es * vy; y1 = ec * vy - es * vx;
            }
            lh[i*4+0] = x0; lh[i*4+1] = y0; lh[i*4+2] = x1; lh[i*4+3] = y1;
        } else {
            x0 = 1.f; y0 = 0.f; x1 = 0.f; y1 = 0.f;
            #pragma unroll
            for (int k = NSTEP - 1; k >= NHARM; --k) {
                const float ec = pc[k], es = ps[k];
                const float px = ec * x0 - es * y0, py = ec * y0 + es * x0;
                const float qx = ec * x1 + es * y1, qy = ec * y1 - es * x1;
                x0 = c * px - s * qy;  y0 = c * py + s * qx;
                x1 = c * qx - s * py;  y1 = c * qy + s * px;
            }
            rh[i*4+0] = x0; rh[i*4+1] = y0; rh[i*4+2] = x1; rh[i*4+3] = y1;
        }
    }
    __syncthreads();

    if (t < 64) {
        const float r0x = lh[t*4], r0y = lh[t*4+1], r1x = lh[t*4+2], r1y = lh[t*4+3];
        const float v0x = rh[t*4], v0y = rh[t*4+1], v1x = rh[t*4+2], v1y = rh[t*4+3];
        const float Px = r0x*v0x - r0y*v0y + r1x*v1x - r1y*v1y;
        const float Py = r0x*v0y + r0y*v0x + r1x*v1y + r1y*v1x;
        gs[t] = s0cs[0] * Px - s0cs[1] * Py;
    }
    __syncthreads();

    // ---- exact 64-pt DFT, 8 accumulators: cos(pi*m/32) = tab[(m+16)&63] ----
    if (t <= NHARM) {
        float a[8] = {0,0,0,0,0,0,0,0};
        #pragma unroll
        for (int k = 0; k < NSAMP; k += 8) {
            #pragma unroll
            for (int j = 0; j < 8; ++j)
                a[j] = fmaf(gs[k+j], tab[(t*(k+j) + 16) & 63], a[j]);
        }
        const float acc = ((a[0]+a[1]) + (a[2]+a[3])) + ((a[4]+a[5]) + (a[6]+a[7]));
        sAB[t].x = acc * ((t == 0) ? (1.0f / 64.0f) : (2.0f / 64.0f));
        if (t == 0) sAB[0].y = 0.0f;
    } else if (t >= 32 && t <= 31 + NHARM) {
        const int j = t - 31;
        float a[8] = {0,0,0,0,0,0,0,0};
        #pragma unroll
        for (int k = 0; k < NSAMP; k += 8) {
            #pragma unroll
            for (int m = 0; m < 8; ++m)
                a[m] = fmaf(gs[k+m], tab[(j*(k+m)) & 63], a[m]);
        }
        sAB[j].y = (((a[0]+a[1]) + (a[2]+a[3])) + ((a[4]+a[5]) + (a[6]+a[7]))) * (2.0f / 64.0f);
    }
    __syncthreads();

    // ---- table: thread t -> grid points t and t+512 (2 indep recurrences) ----
    {
        float suA, cuA, suB, cuB;
        sincospif((float)t * (1.0f / 512.0f), &suA, &cuA);           // u = pi*t/512
        sincospif((float)(t + 512) * (1.0f / 512.0f), &suB, &cuB);
        const float twA = 2.0f * cuA, twB = 2.0f * cuB;

        float b1A = 0.f, b2A = 0.f, d1A = 0.f, d2A = 0.f;
        float b1B = 0.f, b2B = 0.f, d1B = 0.f, d2B = 0.f;

        // 3-deep rolling prefetch (broadcast LDS.64); after loop f0 == sAB[0]
        float2 f0 = sAB[NHARM];
        float2 f1 = sAB[NHARM - 1];
        float2 f2 = sAB[NHARM - 2];

        #pragma unroll
        for (int k = NHARM; k >= 1; --k) {
            const float Ak = f0.x, Bk = f0.y;
            f0 = f1; f1 = f2;
            if (k >= 3) f2 = sAB[k - 3];
            float nb;
            nb = fmaf(twA, b1A, Ak - b2A); b2A = b1A; b1A = nb;
            nb = fmaf(twA, d1A, Bk - d2A); d2A = d1A; d1A = nb;
            nb = fmaf(twB, b1B, Ak - b2B); b2B = b1B; b1B = nb;
            nb = fmaf(twB, d1B, Bk - d2B); d2B = d1B; d1B = nb;
        }

        float gA = f0.x - b2A;
        gA = fmaf(cuA, b1A, gA);
        gA = fmaf(suA, d1A, gA);
        float gB = f0.x - b2B;
        gB = fmaf(cuB, b1B, gB);
        gB = fmaf(suB, d1B, gB);
        g[t]       = gA;
        g[t + 512] = gB;
    }
    __syncthreads();

    // ---- monomial cubic coefficients per interval ----
    #pragma unroll
    for (int r = 0; r < 2; ++r) {
        const int j = t + r * 512;
        const float gm = g[(j + TSIZE - 1) & (TSIZE - 1)];
        const float g0 = g[j];
        const float gp = g[(j + 1) & (TSIZE - 1)];
        const float gq = g[(j + 2) & (TSIZE - 1)];
        const float c1 = gp - gm * (1.0f/3.0f) - g0 * 0.5f - gq * (1.0f/6.0f);
        const float c2 = 0.5f * (gm + gp) - g0;
        const float c3 = (3.0f * (g0 - gp) + gq - gm) * (1.0f/6.0f);
        cf[j] = make_float4(g0, c1, c2, c3);
    }
    __syncthreads();

    // ---- evaluation: range-reduce + LDS.128 + Horner ----
    if (!act) return;

    const float SCALE = (float)TSIZE / 3.14159265358979323846f;
    float th[4] = {xv.x, xv.y, xv.z, xv.w};
    float res[4];
    #pragma unroll
    for (int e = 0; e < 4; ++e) {
        const float u  = th[e] * SCALE;
        const float fl = floorf(u);
        const float f  = u - fl;
        const int idx  = ((int)fl) & (TSIZE - 1);
        const float4 c = cf[idx];
        res[e] = fmaf(fmaf(fmaf(c.w, f, c.z), f, c.y), f, c.x);
    }

    out4[T] = make_float4(fmaf(av.x, res[0], bb), fmaf(av.y, res[1], bb),
                          fmaf(av.z, res[2], bb), fmaf(av.w, res[3], bb));
}

// ---------------------------------------------------------------------------
// Fallback for unexpected shapes (direct chain evaluation).
// ---------------------------------------------------------------------------
__global__ void __launch_bounds__(256)
qsp_generic(const float* __restrict__ x,
            const float* __restrict__ phis,
            const float* __restrict__ alphas,
            const float* __restrict__ bias,
            float* __restrict__ out,
            int n, int nsteps)
{
    __shared__ float pc[256], ps[256];
    __shared__ float s0c, s0s;
    int t = threadIdx.x;
    if (t < nsteps && t < 256) {
        float sp, cp; sincosf(phis[t + 1], &sp, &cp);
        pc[t] = cp; ps[t] = sp;
    }
    if (t == 0) {
        float sp, cp; sincosf(phis[0], &sp, &cp);
        s0c = cp; s0s = sp;
    }
    __syncthreads();

    const int i = blockIdx.x * blockDim.x + t;
    if (i >= n) return;

    float s, c; sincosf(x[i], &s, &c);
    float x0 = 1.0f, y0 = 0.0f, x1 = 0.0f, y1 = 0.0f;
    for (int k = 0; k < nsteps; ++k) {
        const float ec = (k < 256) ? pc[k] : cosf(phis[k + 1]);
        const float es = (k < 256) ? ps[k] : sinf(phis[k + 1]);
        const float ux = c * x0 - s * y1;
        const float uy = c * y0 + s * x1;
        const float vx = c * x1 - s * y0;
        const float vy = c * y1 + s * x0;
        x0 = ec * ux - es * uy;
        y0 = es * ux + ec * uy;
        x1 = ec * vx + es * vy;
        y1 = ec * vy - es * vx;
    }
    const float re = s0c * x0 - s0s * y0;
    out[i] = fmaf(alphas[i], re, bias[0]);
}

extern "C" void kernel_launch(void* const* d_in, const int* in_sizes, int n_in,
                              void* d_out, int out_size)
{
    const float* x      = (const float*)d_in[0];
    const float* phis   = (const float*)d_in[1];
    const float* alphas = (const float*)d_in[2];
    const float* bias   = (const float*)d_in[3];
    float* out = (float*)d_out;

    const int n      = in_sizes[0];
    const int nph    = in_sizes[1];
    const int nsteps = nph - 1;

    if (nsteps == NSTEP && (n & 3) == 0) {
        const int nq      = n >> 2;                   // float4 quads
        const int threads = 512;
        const int blocks  = (nq + threads - 1) / threads;   // 256 for n=524288
        qsp_fused<<<blocks, threads>>>((const float4*)x, phis,
                                       (const float4*)alphas, bias,
                                       (float4*)out, nq);
    } else {
        const int threads = 256;
        const int blocks  = (n + threads - 1) / threads;
        qsp_generic<<<blocks, threads>>>(x, phis, alphas, bias, out, n, nsteps);
    }
}

// round 13
// speedup vs baseline: 1.4588x; 1.1577x over previous
#include <cuda_runtime.h>

// QSP expectation, single fused kernel, zero inter-block communication.
// Base: round-9 structure (best measured), grid 128 x 1024, occ 1.
//
// g(theta) = Re(e^{i phi0} P00) = sum_{j<=27} A_j cos(2j th) + B_j sin(2j th)
//   (pi-periodic, band-limited 54). Per block (one per SM):
//   1) 54-step chain split into two 27-step halves (rows x cols, 128 thr)
//      at 64 samples -> exact table-based 64-pt DFT (8 accumulators).
//   2) 1024-entry table of g: one grid point per thread, scalar Clenshaw
//      with 3-deep float2 coefficient prefetch.
//   3) monomial cubic coefficients per interval; eval = range-reduce +
//      one LDS.128 + 3-fma Horner, 4 elements/thread, early LDGs.

#define NSTEP 54
#define NHARM 27
#define NSAMP 64
#define TSIZE 1024

__global__ void __launch_bounds__(1024, 1)
qsp_fused(const float4* __restrict__ x4,
          const float*  __restrict__ phis,
          const float4* __restrict__ a4,
          const float*  __restrict__ bias,
          float4* __restrict__ out4,
          int nq)                       // nq = n/4
{
    __shared__ float pc[NSTEP], ps[NSTEP];
    __shared__ float s0cs[2];
    __shared__ float lh[64 * 4], rh[64 * 4];      // half-chain results
    __shared__ float gs[NSAMP];                   // g at 64 chain samples
    __shared__ float tab[NSAMP];                  // sinpi table for DFT
    __shared__ __align__(8)  float2 sAB[NHARM + 1];   // (A_k, B_k)
    __shared__ __align__(16) float  g[TSIZE];     // g over one period
    __shared__ __align__(16) float4 cf[TSIZE];    // monomial cubic coeffs

    const int t = threadIdx.x;
    const int T = blockIdx.x * blockDim.x + t;
    const bool act = (T < nq);

    // ---- eval-path global loads issued FIRST ----
    float4 xv = make_float4(0.f, 0.f, 0.f, 0.f);
    float4 av = xv;
    if (act) { xv = x4[T]; av = a4[T]; }
    const float bb = bias[0];

    // ---- phase setup ----
    if (t < NSTEP) {
        float sp, cp; sincosf(phis[t + 1], &sp, &cp);   // accurate, one-time
        pc[t] = cp; ps[t] = sp;
    }
    if (t == 192) {
        float sp, cp; sincosf(phis[0], &sp, &cp);
        s0cs[0] = cp; s0cs[1] = sp;
    }
    if (t >= 128 && t < 128 + NSAMP) {
        const int i = t - 128;
        tab[i] = sinpif((float)i * (1.0f / 32.0f));     // sin(pi*i/32)
    }
    __syncthreads();

    // ---- chain split: threads 0-63 left rows, 64-127 right (transposed) ----
    if (t < 128) {
        const int i = t & 63;
        float s, c; sincospif((float)i * (1.0f / 64.0f), &s, &c);
        float x0, y0, x1, y1;
        if (t < 64) {
            // row r = e0^T * M_1..M_27, iterate r <- r*(W S)
            x0 = 1.f; y0 = 0.f; x1 = 0.f; y1 = 0.f;
            #pragma unroll
            for (int k = 0; k < NHARM; ++k) {
                const float ec = pc[k], es = ps[k];
                const float ux = c * x0 - s * y1, uy = c * y0 + s * x1;
                const float vx = c * x1 - s * y0, vy = c * y1 + s * x0;
                x0 = ec * ux - es * uy; y0 = es * ux + ec * uy;
                x1 = ec * vx + es * vy; y1 = ec * vy - es * vx;
            }
            lh[i*4+0] = x0; lh[i*4+1] = y0; lh[i*4+2] = x1; lh[i*4+3] = y1;
        } else {
            // col v = M_28..M_54 * e0 via transpose rows
            x0 = 1.f; y0 = 0.f; x1 = 0.f; y1 = 0.f;
            #pragma unroll
            for (int k = NSTEP - 1; k >= NHARM; --k) {
                const float ec = pc[k], es = ps[k];
                const float px = ec * x0 - es * y0, py = ec * y0 + es * x0;
                const float qx = ec * x1 + es * y1, qy = ec * y1 - es * x1;
                x0 = c * px - s * qy;  y0 = c * py + s * qx;
                x1 = c * qx - s * py;  y1 = c * qy + s * px;
            }
            rh[i*4+0] = x0; rh[i*4+1] = y0; rh[i*4+2] = x1; rh[i*4+3] = y1;
        }
    }
    __syncthreads();

    if (t < 64) {
        // P00 = r0*v0 + r1*v1 (complex), then Re(e^{i phi0} * P00)
        const float r0x = lh[t*4], r0y = lh[t*4+1], r1x = lh[t*4+2], r1y = lh[t*4+3];
        const float v0x = rh[t*4], v0y = rh[t*4+1], v1x = rh[t*4+2], v1y = rh[t*4+3];
        const float Px = r0x*v0x - r0y*v0y + r1x*v1x - r1y*v1y;
        const float Py = r0x*v0y + r0y*v0x + r1x*v1y + r1y*v1x;
        gs[t] = s0cs[0] * Px - s0cs[1] * Py;
    }
    __syncthreads();

    // ---- exact 64-pt DFT, 8 accumulators: cos(pi*m/32) = tab[(m+16)&63] ----
    if (t <= NHARM) {
        float a[8] = {0,0,0,0,0,0,0,0};
        #pragma unroll
        for (int k = 0; k < NSAMP; k += 8) {
            #pragma unroll
            for (int j = 0; j < 8; ++j)
                a[j] = fmaf(gs[k+j], tab[(t*(k+j) + 16) & 63], a[j]);
        }
        const float acc = ((a[0]+a[1]) + (a[2]+a[3])) + ((a[4]+a[5]) + (a[6]+a[7]));
        sAB[t].x = acc * ((t == 0) ? (1.0f / 64.0f) : (2.0f / 64.0f));
        if (t == 0) sAB[0].y = 0.0f;   // B_0 unused
    } else if (t >= 32 && t <= 31 + NHARM) {
        const int j = t - 31;
        float a[8] = {0,0,0,0,0,0,0,0};
        #pragma unroll
        for (int k = 0; k < NSAMP; k += 8) {
            #pragma unroll
            for (int m = 0; m < 8; ++m)
                a[m] = fmaf(gs[k+m], tab[(j*(k+m)) & 63], a[m]);
        }
        sAB[j].y = (((a[0]+a[1]) + (a[2]+a[3])) + ((a[4]+a[5]) + (a[6]+a[7]))) * (2.0f / 64.0f);
    }
    __syncthreads();

    // ---- table build: thread t evaluates g at grid point t (scalar) ----
    {
        // u = 2*theta_t = pi * t / 512
        float su, cu;
        sincospif((float)t * (1.0f / 512.0f), &su, &cu);
        const float tw = 2.0f * cu;

        float b1 = 0.f, b2 = 0.f, d1 = 0.f, d2 = 0.f;

        // 3-deep rolling prefetch of (A_k,B_k) via LDS.64 (broadcast).
        // Invariant: at iteration k, f0 == sAB[k]; after the loop f0 == sAB[0].
        float2 f0 = sAB[NHARM];
        float2 f1 = sAB[NHARM - 1];
        float2 f2 = sAB[NHARM - 2];

        #pragma unroll
        for (int k = NHARM; k >= 1; --k) {
            const float Ak = f0.x, Bk = f0.y;
            f0 = f1; f1 = f2;
            if (k >= 3) f2 = sAB[k - 3];

            float nb;
            nb = fmaf(tw, b1, Ak - b2); b2 = b1; b1 = nb;
            nb = fmaf(tw, d1, Bk - d2); d2 = d1; d1 = nb;
        }

        float gv = f0.x - b2;              // A0 - b2  (f0 == sAB[0])
        gv = fmaf(cu, b1, gv);
        gv = fmaf(su, d1, gv);
        g[t] = gv;
    }
    __syncthreads();

    // ---- monomial cubic coefficients per interval ----
    {
        const float gm = g[(t + TSIZE - 1) & (TSIZE - 1)];
        const float g0 = g[t];
        const float gp = g[(t + 1) & (TSIZE - 1)];
        const float gq = g[(t + 2) & (TSIZE - 1)];
        const float c1 = gp - gm * (1.0f/3.0f) - g0 * 0.5f - gq * (1.0f/6.0f);
        const float c2 = 0.5f * (gm + gp) - g0;
        const float c3 = (3.0f * (g0 - gp) + gq - gm) * (1.0f/6.0f);
        cf[t] = make_float4(g0, c1, c2, c3);
    }
    __syncthreads();

    // ---- evaluation: range-reduce + LDS.128 + 3-fma Horner ----
    if (!act) return;

    const float SCALE = (float)TSIZE / 3.14159265358979323846f;
    float th[4] = {xv.x, xv.y, xv.z, xv.w};
    float res[4];
    #pragma unroll
    for (int e = 0; e < 4; ++e) {
        const float u  = th[e] * SCALE;
        const float fl = floorf(u);
        const float f  = u - fl;
        const int idx  = ((int)fl) & (TSIZE - 1);
        const float4 c = cf[idx];
        res[e] = fmaf(fmaf(fmaf(c.w, f, c.z), f, c.y), f, c.x);
    }

    out4[T] = make_float4(fmaf(av.x, res[0], bb), fmaf(av.y, res[1], bb),
                          fmaf(av.z, res[2], bb), fmaf(av.w, res[3], bb));
}

// ---------------------------------------------------------------------------
// Fallback for unexpected shapes (direct chain evaluation).
// ---------------------------------------------------------------------------
__global__ void __launch_bounds__(256)
qsp_generic(const float* __restrict__ x,
            const float* __restrict__ phis,
            const float* __restrict__ alphas,
            const float* __restrict__ bias,
            float* __restrict__ out,
            int n, int nsteps)
{
    __shared__ float pc[256], ps[256];
    __shared__ float s0c, s0s;
    int t = threadIdx.x;
    if (t < nsteps && t < 256) {
        float sp, cp; sincosf(phis[t + 1], &sp, &cp);
        pc[t] = cp; ps[t] = sp;
    }
    if (t == 0) {
        float sp, cp; sincosf(phis[0], &sp, &cp);
        s0c = cp; s0s = sp;
    }
    __syncthreads();

    const int i = blockIdx.x * blockDim.x + t;
    if (i >= n) return;

    float s, c; sincosf(x[i], &s, &c);
    float x0 = 1.0f, y0 = 0.0f, x1 = 0.0f, y1 = 0.0f;
    for (int k = 0; k < nsteps; ++k) {
        const float ec = (k < 256) ? pc[k] : cosf(phis[k + 1]);
        const float es = (k < 256) ? ps[k] : sinf(phis[k + 1]);
        const float ux = c * x0 - s * y1;
        const float uy = c * y0 + s * x1;
        const float vx = c * x1 - s * y0;
        const float vy = c * y1 + s * x0;
        x0 = ec * ux - es * uy;
        y0 = es * ux + ec * uy;
        x1 = ec * vx + es * vy;
        y1 = ec * vy - es * vx;
    }
    const float re = s0c * x0 - s0s * y0;
    out[i] = fmaf(alphas[i], re, bias[0]);
}

extern "C" void kernel_launch(void* const* d_in, const int* in_sizes, int n_in,
                              void* d_out, int out_size)
{
    const float* x      = (const float*)d_in[0];
    const float* phis   = (const float*)d_in[1];
    const float* alphas = (const float*)d_in[2];
    const float* bias   = (const float*)d_in[3];
    float* out = (float*)d_out;

    const int n      = in_sizes[0];
    const int nph    = in_sizes[1];
    const int nsteps = nph - 1;

    if (nsteps == NSTEP && (n & 3) == 0) {
        const int nq      = n >> 2;                   // float4 quads
        const int threads = 1024;
        const int blocks  = (nq + threads - 1) / threads;   // 128 for n=524288
        qsp_fused<<<blocks, threads>>>((const float4*)x, phis,
                                       (const float4*)alphas, bias,
                                       (float4*)out, nq);
    } else {
        const int threads = 256;
        const int blocks  = (n + threads - 1) / threads;
        qsp_generic<<<blocks, threads>>>(x, phis, alphas, bias, out, n, nsteps);
    }
}

// round 14
// speedup vs baseline: 1.4963x; 1.0257x over previous
#include <cuda_runtime.h>

// QSP expectation, single fused kernel, zero inter-block communication.
// Grid 128 x 1024 (one block per SM).
//
// g(theta) = Re(e^{i phi0} P00) = sum_{j<=27} A_j cos(2j th) + B_j sin(2j th)
//   (pi-periodic, band-limited 54). Per block:
//   1) threads 0-127 run the whole coefficient pipeline (setup -> split
//      27+27-step chain -> P00 dot -> exact table-based 64-pt DFT) using
//      NAMED partial barriers (bar.sync 1,128); only 3 full barriers remain.
//   2) 512-entry table of g: threads 0-511, scalar Clenshaw, 3-deep
//      float2 coefficient prefetch.
//   3) monomial cubic coeffs per interval; eval = range-reduce + one
//      LDS.128 + 3-fma Horner, 4 elements/thread, early LDGs.

#define NSTEP 54
#define NHARM 27
#define NSAMP 64
#define TSIZE 512

__device__ __forceinline__ void bar128() {
    asm volatile("bar.sync 1, 128;" ::: "memory");
}

__global__ void __launch_bounds__(1024, 1)
qsp_fused(const float4* __restrict__ x4,
          const float*  __restrict__ phis,
          const float4* __restrict__ a4,
          const float*  __restrict__ bias,
          float4* __restrict__ out4,
          int nq)                       // nq = n/4
{
    __shared__ float pc[NSTEP], ps[NSTEP];
    __shared__ float s0cs[2];
    __shared__ float lh[64 * 4], rh[64 * 4];      // half-chain results
    __shared__ float gs[NSAMP];                   // g at 64 chain samples
    __shared__ float tab[NSAMP];                  // sinpi table for DFT
    __shared__ __align__(8)  float2 sAB[NHARM + 1];   // (A_k, B_k)
    __shared__ __align__(16) float  g[TSIZE];     // g over one period
    __shared__ __align__(16) float4 cf[TSIZE];    // monomial cubic coeffs

    const int t = threadIdx.x;
    const int T = blockIdx.x * blockDim.x + t;
    const bool act = (T < nq);

    // ---- eval-path global loads issued FIRST ----
    float4 xv = make_float4(0.f, 0.f, 0.f, 0.f);
    float4 av = xv;
    if (act) { xv = x4[T]; av = a4[T]; }
    const float bb = bias[0];

    // ================= narrow pipeline: threads 0-127 only =================
    if (t < 128) {
        // ---- setup: all inputs produced INSIDE threads 0-127 ----
        if (t < NSTEP) {
            float sp, cp; sincosf(phis[t + 1], &sp, &cp);   // accurate, one-time
            pc[t] = cp; ps[t] = sp;
        }
        if (t == 63) {
            float sp, cp; sincosf(phis[0], &sp, &cp);
            s0cs[0] = cp; s0cs[1] = sp;
        }
        if (t >= 64) {
            const int i = t - 64;
            tab[i] = sinpif((float)i * (1.0f / 32.0f));     // sin(pi*i/32)
        }
        bar128();

        // ---- chain split: 0-63 left rows, 64-127 right cols (transposed) ----
        {
            const int i = t & 63;
            float s, c; sincospif((float)i * (1.0f / 64.0f), &s, &c);
            float x0, y0, x1, y1;
            if (t < 64) {
                x0 = 1.f; y0 = 0.f; x1 = 0.f; y1 = 0.f;
                #pragma unroll
                for (int k = 0; k < NHARM; ++k) {
                    const float ec = pc[k], es = ps[k];
                    const float ux = c * x0 - s * y1, uy = c * y0 + s * x1;
                    const float vx = c * x1 - s * y0, vy = c * y1 + s * x0;
                    x0 = ec * ux - es * uy; y0 = es * ux + ec * uy;
                    x1 = ec * vx + es * vy; y1 = ec * vy - es * vx;
                }
                lh[i*4+0] = x0; lh[i*4+1] = y0; lh[i*4+2] = x1; lh[i*4+3] = y1;
            } else {
                x0 = 1.f; y0 = 0.f; x1 = 0.f; y1 = 0.f;
                #pragma unroll
                for (int k = NSTEP - 1; k >= NHARM; --k) {
                    const float ec = pc[k], es = ps[k];
                    const float px = ec * x0 - es * y0, py = ec * y0 + es * x0;
                    const float qx = ec * x1 + es * y1, qy = ec * y1 - es * x1;
                    x0 = c * px - s * qy;  y0 = c * py + s * qx;
                    x1 = c * qx - s * py;  y1 = c * qy + s * px;
                }
                rh[i*4+0] = x0; rh[i*4+1] = y0; rh[i*4+2] = x1; rh[i*4+3] = y1;
            }
        }
        bar128();

        // ---- P00 dot: g at the 64 chain samples ----
        if (t < 64) {
            const float r0x = lh[t*4], r0y = lh[t*4+1], r1x = lh[t*4+2], r1y = lh[t*4+3];
            const float v0x = rh[t*4], v0y = rh[t*4+1], v1x = rh[t*4+2], v1y = rh[t*4+3];
            const float Px = r0x*v0x - r0y*v0y + r1x*v1x - r1y*v1y;
            const float Py = r0x*v0y + r0y*v0x + r1x*v1y + r1y*v1x;
            gs[t] = s0cs[0] * Px - s0cs[1] * Py;
        }
        bar128();

        // ---- exact 64-pt DFT, 8 accumulators: cos(pi*m/32)=tab[(m+16)&63] ----
        if (t <= NHARM) {
            float a[8] = {0,0,0,0,0,0,0,0};
            #pragma unroll
            for (int k = 0; k < NSAMP; k += 8) {
                #pragma unroll
                for (int j = 0; j < 8; ++j)
                    a[j] = fmaf(gs[k+j], tab[(t*(k+j) + 16) & 63], a[j]);
            }
            const float acc = ((a[0]+a[1]) + (a[2]+a[3])) + ((a[4]+a[5]) + (a[6]+a[7]));
            sAB[t].x = acc * ((t == 0) ? (1.0f / 64.0f) : (2.0f / 64.0f));
            if (t == 0) sAB[0].y = 0.0f;   // B_0 unused
        } else if (t >= 32 && t <= 31 + NHARM) {
            const int j = t - 31;
            float a[8] = {0,0,0,0,0,0,0,0};
            #pragma unroll
            for (int k = 0; k < NSAMP; k += 8) {
                #pragma unroll
                for (int m = 0; m < 8; ++m)
                    a[m] = fmaf(gs[k+m], tab[(j*(k+m)) & 63], a[m]);
            }
            sAB[j].y = (((a[0]+a[1]) + (a[2]+a[3])) + ((a[4]+a[5]) + (a[6]+a[7]))) * (2.0f / 64.0f);
        }
    }
    __syncthreads();   // sAB ready for the whole block

    // ---- table build: threads 0-511, one grid point each ----
    if (t < TSIZE) {
        // u = 2*theta_t = pi * t / 256
        float su, cu;
        sincospif((float)t * (1.0f / 256.0f), &su, &cu);
        const float tw = 2.0f * cu;

        float b1 = 0.f, b2 = 0.f, d1 = 0.f, d2 = 0.f;

        // 3-deep rolling prefetch (broadcast LDS.64); after loop f0 == sAB[0]
        float2 f0 = sAB[NHARM];
        float2 f1 = sAB[NHARM - 1];
        float2 f2 = sAB[NHARM - 2];

        #pragma unroll
        for (int k = NHARM; k >= 1; --k) {
            const float Ak = f0.x, Bk = f0.y;
            f0 = f1; f1 = f2;
            if (k >= 3) f2 = sAB[k - 3];

            float nb;
            nb = fmaf(tw, b1, Ak - b2); b2 = b1; b1 = nb;
            nb = fmaf(tw, d1, Bk - d2); d2 = d1; d1 = nb;
        }

        float gv = f0.x - b2;              // A0 - b2  (f0 == sAB[0])
        gv = fmaf(cu, b1, gv);
        gv = fmaf(su, d1, gv);
        g[t] = gv;
    }
    __syncthreads();

    // ---- monomial cubic coefficients per interval (threads 0-511) ----
    if (t < TSIZE) {
        const float gm = g[(t + TSIZE - 1) & (TSIZE - 1)];
        const float g0 = g[t];
        const float gp = g[(t + 1) & (TSIZE - 1)];
        const float gq = g[(t + 2) & (TSIZE - 1)];
        const float c1 = gp - gm * (1.0f/3.0f) - g0 * 0.5f - gq * (1.0f/6.0f);
        const float c2 = 0.5f * (gm + gp) - g0;
        const float c3 = (3.0f * (g0 - gp) + gq - gm) * (1.0f/6.0f);
        cf[t] = make_float4(g0, c1, c2, c3);
    }
    __syncthreads();

    // ---- evaluation: range-reduce + LDS.128 + 3-fma Horner ----
    if (!act) return;

    const float SCALE = (float)TSIZE / 3.14159265358979323846f;
    float th[4] = {xv.x, xv.y, xv.z, xv.w};
    float res[4];
    #pragma unroll
    for (int e = 0; e < 4; ++e) {
        const float u  = th[e] * SCALE;
        const float fl = floorf(u);
        const float f  = u - fl;
        const int idx  = ((int)fl) & (TSIZE - 1);
        const float4 c = cf[idx];
        res[e] = fmaf(fmaf(fmaf(c.w, f, c.z), f, c.y), f, c.x);
    }

    out4[T] = make_float4(fmaf(av.x, res[0], bb), fmaf(av.y, res[1], bb),
                          fmaf(av.z, res[2], bb), fmaf(av.w, res[3], bb));
}

// ---------------------------------------------------------------------------
// Fallback for unexpected shapes (direct chain evaluation).
// ---------------------------------------------------------------------------
__global__ void __launch_bounds__(256)
qsp_generic(const float* __restrict__ x,
            const float* __restrict__ phis,
            const float* __restrict__ alphas,
            const float* __restrict__ bias,
            float* __restrict__ out,
            int n, int nsteps)
{
    __shared__ float pc[256], ps[256];
    __shared__ float s0c, s0s;
    int t = threadIdx.x;
    if (t < nsteps && t < 256) {
        float sp, cp; sincosf(phis[t + 1], &sp, &cp);
        pc[t] = cp; ps[t] = sp;
    }
    if (t == 0) {
        float sp, cp; sincosf(phis[0], &sp, &cp);
        s0c = cp; s0s = sp;
    }
    __syncthreads();

    const int i = blockIdx.x * blockDim.x + t;
    if (i >= n) return;

    float s, c; sincosf(x[i], &s, &c);
    float x0 = 1.0f, y0 = 0.0f, x1 = 0.0f, y1 = 0.0f;
    for (int k = 0; k < nsteps; ++k) {
        const float ec = (k < 256) ? pc[k] : cosf(phis[k + 1]);
        const float es = (k < 256) ? ps[k] : sinf(phis[k + 1]);
        const float ux = c * x0 - s * y1;
        const float uy = c * y0 + s * x1;
        const float vx = c * x1 - s * y0;
        const float vy = c * y1 + s * x0;
        x0 = ec * ux - es * uy;
        y0 = es * ux + ec * uy;
        x1 = ec * vx + es * vy;
        y1 = ec * vy - es * vx;
    }
    const float re = s0c * x0 - s0s * y0;
    out[i] = fmaf(alphas[i], re, bias[0]);
}

extern "C" void kernel_launch(void* const* d_in, const int* in_sizes, int n_in,
                              void* d_out, int out_size)
{
    const float* x      = (const float*)d_in[0];
    const float* phis   = (const float*)d_in[1];
    const float* alphas = (const float*)d_in[2];
    const float* bias   = (const float*)d_in[3];
    float* out = (float*)d_out;

    const int n      = in_sizes[0];
    const int nph    = in_sizes[1];
    const int nsteps = nph - 1;

    if (nsteps == NSTEP && (n & 3) == 0) {
        const int nq      = n >> 2;                   // float4 quads
        const int threads = 1024;
        const int blocks  = (nq + threads - 1) / threads;   // 128 for n=524288
        qsp_fused<<<blocks, threads>>>((const float4*)x, phis,
                                       (const float4*)alphas, bias,
                                       (float4*)out, nq);
    } else {
        const int threads = 256;
        const int blocks  = (n + threads - 1) / threads;
        qsp_generic<<<blocks, threads>>>(x, phis, alphas, bias, out, n, nsteps);
    }
}